// round 2
// baseline (speedup 1.0000x reference)
#include <cuda_runtime.h>

// RX2: apply RX(theta_q) to each of 20 qubits of a [16, 2^20] state vector.
// Qubit q pairs amplitudes at stride 2^(19-q). All gates commute.
//
// Pass 1: bits 0..12  (qubits 19..7), contiguous 8192-amp tiles, 3 smem rounds,
//         reads real phi, writes complex (float2) into d_out.
// Pass 2: bits 13..19 (qubits 6..0), tiles = 128 strided rows x 64 contiguous,
//         1 smem round, in-place on d_out (disjoint tiles per CTA).

#define NQ 20

__device__ __forceinline__ void bfly(float& ar, float& ai, float& br, float& bi,
                                     float c, float s) {
    // na = c*a + (-i s)*b ; nb = (-i s)*a + c*b
    float nar = c * ar + s * bi;
    float nai = c * ai - s * br;
    float nbr = c * br + s * ai;
    float nbi = c * bi - s * ar;
    ar = nar; ai = nai; br = nbr; bi = nbi;
}

// -------------------------------------------------------------------------
// Pass 1: strides 1..4096 (qubits 19..7). Tile = 8192 contiguous amplitudes.
// 512 threads, 16 amplitudes per thread.
//   Round A: thread owns idx bits 0..3  (coalesced float4 global load)
//   Round B: thread owns idx bits 4..7
//   Round C: thread owns idx bits 8..11
//   Final : stage for bit 12 fused with coalesced float2 global store
// Smem padding: pidx = i + (i>>5) (stride-16 accesses conflict-free).
// -------------------------------------------------------------------------
__global__ __launch_bounds__(512, 2)
void rx_pass1(const float* __restrict__ phi,
              const float* __restrict__ thetas,
              float2* __restrict__ out)
{
    extern __shared__ float sm1[];
    float* sre = sm1;          // 8448 floats
    float* sim = sm1 + 8448;   // 8448 floats
    __shared__ float cB[13], sB[13];

    const int t    = threadIdx.x;
    const int b    = blockIdx.y;
    const int tile = blockIdx.x;
    const size_t base = ((size_t)b << 20) + ((size_t)tile << 13);

    if (t < 13) {
        // stage k (stride 2^k) uses qubit 19-k
        float th = 0.5f * thetas[b * NQ + (19 - t)];
        float sv, cv;
        sincosf(th, &sv, &cv);
        sB[t] = sv; cB[t] = cv;
    }

    float re[16], im[16];

    // ---- Round A: load (real input), idx = 16*t + j ----
    const float4* pin = (const float4*)(phi + base + ((size_t)t << 4));
    #pragma unroll
    for (int q = 0; q < 4; q++) {
        float4 v = pin[q];
        re[4*q+0] = v.x; re[4*q+1] = v.y; re[4*q+2] = v.z; re[4*q+3] = v.w;
        im[4*q+0] = 0.f; im[4*q+1] = 0.f; im[4*q+2] = 0.f; im[4*q+3] = 0.f;
    }
    __syncthreads();   // cB/sB visible

    #pragma unroll
    for (int k = 0; k < 4; k++) {
        float c = cB[k], s = sB[k];
        const int m = 1 << k;
        #pragma unroll
        for (int j = 0; j < 16; j++)
            if (!(j & m)) bfly(re[j], im[j], re[j | m], im[j | m], c, s);
    }
    #pragma unroll
    for (int j = 0; j < 16; j++) {
        int i = (t << 4) + j; int p = i + (i >> 5);
        sre[p] = re[j]; sim[p] = im[j];
    }
    __syncthreads();

    // ---- Round B: idx = (t&15) | (j<<4) | ((t>>4)<<8) ----
    #pragma unroll
    for (int j = 0; j < 16; j++) {
        int i = (t & 15) | (j << 4) | ((t >> 4) << 8); int p = i + (i >> 5);
        re[j] = sre[p]; im[j] = sim[p];
    }
    #pragma unroll
    for (int k = 4; k < 8; k++) {
        float c = cB[k], s = sB[k];
        const int m = 1 << (k - 4);
        #pragma unroll
        for (int j = 0; j < 16; j++)
            if (!(j & m)) bfly(re[j], im[j], re[j | m], im[j | m], c, s);
    }
    #pragma unroll
    for (int j = 0; j < 16; j++) {
        int i = (t & 15) | (j << 4) | ((t >> 4) << 8); int p = i + (i >> 5);
        sre[p] = re[j]; sim[p] = im[j];
    }
    __syncthreads();

    // ---- Round C: idx = (t&255) | (j<<8) | ((t>>8)<<12) ----
    #pragma unroll
    for (int j = 0; j < 16; j++) {
        int i = (t & 255) | (j << 8) | ((t >> 8) << 12); int p = i + (i >> 5);
        re[j] = sre[p]; im[j] = sim[p];
    }
    #pragma unroll
    for (int k = 8; k < 12; k++) {
        float c = cB[k], s = sB[k];
        const int m = 1 << (k - 8);
        #pragma unroll
        for (int j = 0; j < 16; j++)
            if (!(j & m)) bfly(re[j], im[j], re[j | m], im[j | m], c, s);
    }
    #pragma unroll
    for (int j = 0; j < 16; j++) {
        int i = (t & 255) | (j << 8) | ((t >> 8) << 12); int p = i + (i >> 5);
        sre[p] = re[j]; sim[p] = im[j];
    }
    __syncthreads();

    // ---- Final stage: bit 12 (qubit 7), fused with global store ----
    {
        float2* po = out + base;
        const float c = cB[12], s = sB[12];
        #pragma unroll
        for (int jj = 0; jj < 8; jj++) {
            int p  = (jj << 9) + t;         // 0..4095, warp-consecutive
            int pb = p + 4096;
            int ia = p  + (p  >> 5);
            int ib = pb + (pb >> 5);
            float ar = sre[ia], ai = sim[ia];
            float br = sre[ib], bi = sim[ib];
            bfly(ar, ai, br, bi, c, s);
            po[p]  = make_float2(ar, ai);
            po[pb] = make_float2(br, bi);
        }
    }
}

// -------------------------------------------------------------------------
// Pass 2: strides 8192..2^19 (qubits 6..0), in place on d_out.
// Tile: h = 0..127 (bits 13..19), c = 0..63 contiguous (bits 0..5 of the
// chunk). 512 threads, 16 amplitudes each, one smem exchange.
//   Round A: thread owns h bits 0..3  -> stages m=0..3 (qubits 6..3)
//   Round B: thread owns h bits 3..6  -> stages m=4..6 (qubits 2..0)
// All smem accesses lane-consecutive in c: conflict-free, no padding.
// -------------------------------------------------------------------------
__global__ __launch_bounds__(512, 2)
void rx_pass2(const float* __restrict__ thetas,
              float2* __restrict__ out)
{
    extern __shared__ float sm2[];
    float* sre = sm2;          // 8192 floats
    float* sim = sm2 + 8192;
    __shared__ float cB[7], sB[7];

    const int t     = threadIdx.x;
    const int b     = blockIdx.y;
    const int chunk = blockIdx.x;          // covers idx bits 6..12

    if (t < 7) {
        // stage m (h-stride 2^m, global stride 2^(13+m)) uses qubit 6-m
        float th = 0.5f * thetas[b * NQ + (6 - t)];
        float sv, cv;
        sincosf(th, &sv, &cv);
        sB[t] = sv; cB[t] = cv;
    }

    float2* pg = out + ((size_t)b << 20) + ((size_t)chunk << 6);
    const int c  = t & 63;
    const int h0 = t >> 6;     // 0..7

    float re[16], im[16];

    // ---- Round A: h = j | (h0<<4) ; coalesced 256B-per-warp loads ----
    #pragma unroll
    for (int j = 0; j < 16; j++) {
        int h = j | (h0 << 4);
        float2 v = pg[((size_t)h << 13) + c];
        re[j] = v.x; im[j] = v.y;
    }
    __syncthreads();   // cB/sB visible

    #pragma unroll
    for (int m = 0; m < 4; m++) {
        float cc = cB[m], ss = sB[m];
        const int st = 1 << m;
        #pragma unroll
        for (int j = 0; j < 16; j++)
            if (!(j & st)) bfly(re[j], im[j], re[j | st], im[j | st], cc, ss);
    }
    #pragma unroll
    for (int j = 0; j < 16; j++) {
        int h = j | (h0 << 4);
        int i = (h << 6) + c;
        sre[i] = re[j]; sim[i] = im[j];
    }
    __syncthreads();

    // ---- Round B: h = h0 | (j<<3) ----
    #pragma unroll
    for (int j = 0; j < 16; j++) {
        int h = h0 | (j << 3);
        int i = (h << 6) + c;
        re[j] = sre[i]; im[j] = sim[i];
    }
    #pragma unroll
    for (int m = 4; m < 7; m++) {
        float cc = cB[m], ss = sB[m];
        const int st = 1 << (m - 3);   // h-bit m lives at j-bit (m-3)
        #pragma unroll
        for (int j = 0; j < 16; j++)
            if (!(j & st)) bfly(re[j], im[j], re[j | st], im[j | st], cc, ss);
    }
    // ---- store (coalesced 256B per warp per j) ----
    #pragma unroll
    for (int j = 0; j < 16; j++) {
        int h = h0 | (j << 3);
        pg[((size_t)h << 13) + c] = make_float2(re[j], im[j]);
    }
}

extern "C" void kernel_launch(void* const* d_in, const int* in_sizes, int n_in,
                              void* d_out, int out_size)
{
    const float* phi    = (const float*)d_in[0];   // [16, 2^20] float32
    const float* thetas = (const float*)d_in[1];   // [16, 20]   float32
    float2* out = (float2*)d_out;                  // [16, 2^20] (re, im)

    // Dynamic smem > 48KB needs the attribute. Idempotent, capture-safe.
    cudaFuncSetAttribute(rx_pass1, cudaFuncAttributeMaxDynamicSharedMemorySize,
                         2 * 8448 * (int)sizeof(float));
    cudaFuncSetAttribute(rx_pass2, cudaFuncAttributeMaxDynamicSharedMemorySize,
                         2 * 8192 * (int)sizeof(float));

    dim3 grid(128, 16);
    rx_pass1<<<grid, 512, 2 * 8448 * sizeof(float)>>>(phi, thetas, out);
    rx_pass2<<<grid, 512, 2 * 8192 * sizeof(float)>>>(thetas, out);
}

// round 5
// speedup vs baseline: 1.6868x; 1.6868x over previous
#include <cuda_runtime.h>

// RX2: apply RX(theta_q) to each of 20 qubits of [16, 2^20] states.
// Stage k pairs amplitudes at stride 2^k and uses qubit 19-k.
//
// Amplitudes are held PACKED (re,im) in 64-bit values and processed with
// sm_103a f32x2 packed FMA: 4 fma-pipe instructions per butterfly (vs 8
// scalar). Global float2 and SMEM traffic are single b64 accesses.
//
// Pass 1: stages 0..12, contiguous 8192-amp tiles, 3 smem exchanges.
// Pass 2: stages 13..19, tiles = 128 strided rows x 64 contiguous, 1 exchange.
// Launched per 8-batch group (p1 then p2) so pass2 reads pass1's output
// out of L2 (64MB group working set < 126MB L2).

#define NQ 20
typedef unsigned long long u64;

__device__ __forceinline__ u64 pk2(float x, float y) {
    u64 v; asm("mov.b64 %0, {%1, %2};" : "=l"(v) : "f"(x), "f"(y)); return v;
}
__device__ __forceinline__ u64 swp(u64 v) {
    float x, y;
    asm("mov.b64 {%0, %1}, %2;" : "=f"(x), "=f"(y) : "l"(v));
    return pk2(y, x);
}
__device__ __forceinline__ u64 fma2(u64 a, u64 b, u64 c) {
    u64 d; asm("fma.rn.f32x2 %0, %1, %2, %3;" : "=l"(d) : "l"(a), "l"(b), "l"(c)); return d;
}
__device__ __forceinline__ u64 mul2(u64 a, u64 b) {
    u64 d; asm("mul.rn.f32x2 %0, %1, %2;" : "=l"(d) : "l"(a), "l"(b)); return d;
}

// a=(ar,ai), b=(br,bi); c2=(c,c), s2=(s,-s)
// na = (c*ar + s*bi, c*ai - s*br) = c2*a + s2*swap(b)
// nb = (c*br + s*ai, c*bi - s*ar) = c2*b + s2*swap(a)
__device__ __forceinline__ void bfly2(u64& a, u64& b, u64 c2, u64 s2) {
    u64 na = fma2(c2, a, mul2(s2, swp(b)));
    u64 nb = fma2(c2, b, mul2(s2, swp(a)));
    a = na; b = nb;
}

// -------------------------------------------------------------------------
// Pass 1: stages 0..12 (qubits 19..7). Tile = 8192 contiguous amplitudes.
// 512 threads, 16 amps/thread. Rounds: bits 0-3 / 4-7 / 8-11, final stage
// (bit 12) fused with the global store.
// Pad p = i + (i>>4): conflict-free half-warp phases for 64-bit LDS/STS.
// -------------------------------------------------------------------------
__global__ __launch_bounds__(512, 2)
void rx_pass1(const float* __restrict__ phi,
              const float* __restrict__ thetas,
              u64* __restrict__ out, int b0)
{
    extern __shared__ u64 sm[];              // 8704 u64 (8192 + pad)
    __shared__ u64 c2B[13], s2B[13];

    const int t    = threadIdx.x;
    const int b    = b0 + blockIdx.y;
    const int tile = blockIdx.x;
    const size_t base = ((size_t)b << 20) + ((size_t)tile << 13);

    if (t < 13) {
        float sv, cv;
        sincosf(0.5f * thetas[b * NQ + (19 - t)], &sv, &cv);
        c2B[t] = pk2(cv, cv);
        s2B[t] = pk2(sv, -sv);
    }

    u64 amp[16];

    // ---- Round A: load real input, idx = 16*t + j ----
    const float4* pin = (const float4*)(phi + base + ((size_t)t << 4));
    #pragma unroll
    for (int q = 0; q < 4; q++) {
        float4 v = pin[q];
        amp[4*q+0] = pk2(v.x, 0.f);
        amp[4*q+1] = pk2(v.y, 0.f);
        amp[4*q+2] = pk2(v.z, 0.f);
        amp[4*q+3] = pk2(v.w, 0.f);
    }
    __syncthreads();   // c2B/s2B visible

    #pragma unroll
    for (int k = 0; k < 4; k++) {
        const u64 c2 = c2B[k], s2 = s2B[k];
        const int m = 1 << k;
        #pragma unroll
        for (int j = 0; j < 16; j++)
            if (!(j & m)) bfly2(amp[j], amp[j | m], c2, s2);
    }
    #pragma unroll
    for (int j = 0; j < 16; j++) {
        int i = (t << 4) + j;
        sm[i + (i >> 4)] = amp[j];
    }
    __syncthreads();

    // ---- Round B: idx = (t&15) | (j<<4) | ((t>>4)<<8) ----
    #pragma unroll
    for (int j = 0; j < 16; j++) {
        int i = (t & 15) | (j << 4) | ((t >> 4) << 8);
        amp[j] = sm[i + (i >> 4)];
    }
    #pragma unroll
    for (int k = 4; k < 8; k++) {
        const u64 c2 = c2B[k], s2 = s2B[k];
        const int m = 1 << (k - 4);
        #pragma unroll
        for (int j = 0; j < 16; j++)
            if (!(j & m)) bfly2(amp[j], amp[j | m], c2, s2);
    }
    __syncthreads();   // all round-B reads done before rewrites
    #pragma unroll
    for (int j = 0; j < 16; j++) {
        int i = (t & 15) | (j << 4) | ((t >> 4) << 8);
        sm[i + (i >> 4)] = amp[j];
    }
    __syncthreads();

    // ---- Round C: idx = (t&255) | (j<<8) | ((t>>8)<<12) ----
    #pragma unroll
    for (int j = 0; j < 16; j++) {
        int i = (t & 255) | (j << 8) | ((t >> 8) << 12);
        amp[j] = sm[i + (i >> 4)];
    }
    #pragma unroll
    for (int k = 8; k < 12; k++) {
        const u64 c2 = c2B[k], s2 = s2B[k];
        const int m = 1 << (k - 8);
        #pragma unroll
        for (int j = 0; j < 16; j++)
            if (!(j & m)) bfly2(amp[j], amp[j | m], c2, s2);
    }
    __syncthreads();
    #pragma unroll
    for (int j = 0; j < 16; j++) {
        int i = (t & 255) | (j << 8) | ((t >> 8) << 12);
        sm[i + (i >> 4)] = amp[j];
    }
    __syncthreads();

    // ---- Final stage: bit 12 (qubit 7), fused with coalesced b64 store ----
    {
        u64* po = out + base;
        const u64 c2 = c2B[12], s2 = s2B[12];
        #pragma unroll
        for (int jj = 0; jj < 8; jj++) {
            int p  = (jj << 9) + t;          // 0..4095, warp-consecutive
            int pb = p + 4096;
            u64 a = sm[p  + (p  >> 4)];
            u64 bb = sm[pb + (pb >> 4)];
            bfly2(a, bb, c2, s2);
            po[p]  = a;
            po[pb] = bb;
        }
    }
}

// -------------------------------------------------------------------------
// Pass 2: stages 13..19 (qubits 6..0), in place on out.
// Tile: h = 0..127 (bits 13..19) x 64 contiguous (bits 0..5 of chunk).
// 512 threads, 16 amps/thread, one smem exchange. All smem accesses are
// lane-consecutive in c: conflict-free.
// -------------------------------------------------------------------------
__global__ __launch_bounds__(512, 2)
void rx_pass2(const float* __restrict__ thetas,
              u64* __restrict__ out, int b0)
{
    extern __shared__ u64 sm2[];             // 8192 u64
    __shared__ u64 c2B[7], s2B[7];

    const int t     = threadIdx.x;
    const int b     = b0 + blockIdx.y;
    const int chunk = blockIdx.x;            // idx bits 6..12

    if (t < 7) {
        // stage m (h-stride 2^m = global stride 2^(13+m)) uses qubit 6-m
        float sv, cv;
        sincosf(0.5f * thetas[b * NQ + (6 - t)], &sv, &cv);
        c2B[t] = pk2(cv, cv);
        s2B[t] = pk2(sv, -sv);
    }

    u64* pg = out + ((size_t)b << 20) + ((size_t)chunk << 6);
    const int c  = t & 63;
    const int h0 = t >> 6;                   // 0..7

    u64 amp[16];

    // ---- Round A: h = j | (h0<<4) ; 512B-per-warp coalesced b64 loads ----
    #pragma unroll
    for (int j = 0; j < 16; j++) {
        int h = j | (h0 << 4);
        amp[j] = pg[((size_t)h << 13) + c];
    }
    __syncthreads();   // c2B/s2B visible

    #pragma unroll
    for (int m = 0; m < 4; m++) {
        const u64 c2 = c2B[m], s2 = s2B[m];
        const int st = 1 << m;
        #pragma unroll
        for (int j = 0; j < 16; j++)
            if (!(j & st)) bfly2(amp[j], amp[j | st], c2, s2);
    }
    #pragma unroll
    for (int j = 0; j < 16; j++) {
        int h = j | (h0 << 4);
        sm2[(h << 6) + c] = amp[j];
    }
    __syncthreads();

    // ---- Round B: h = h0 | (j<<3) ----
    #pragma unroll
    for (int j = 0; j < 16; j++) {
        int h = h0 | (j << 3);
        amp[j] = sm2[(h << 6) + c];
    }
    #pragma unroll
    for (int m = 4; m < 7; m++) {
        const u64 c2 = c2B[m], s2 = s2B[m];
        const int st = 1 << (m - 3);         // h-bit m lives at j-bit (m-3)
        #pragma unroll
        for (int j = 0; j < 16; j++)
            if (!(j & st)) bfly2(amp[j], amp[j | st], c2, s2);
    }
    // ---- store (coalesced b64) ----
    #pragma unroll
    for (int j = 0; j < 16; j++) {
        int h = h0 | (j << 3);
        pg[((size_t)h << 13) + c] = amp[j];
    }
}

extern "C" void kernel_launch(void* const* d_in, const int* in_sizes, int n_in,
                              void* d_out, int out_size)
{
    const float* phi    = (const float*)d_in[0];   // [16, 2^20] float32
    const float* thetas = (const float*)d_in[1];   // [16, 20]   float32
    u64* out = (u64*)d_out;                        // [16, 2^20] packed (re,im)

    const int SM1 = 8704 * (int)sizeof(u64);       // 69632 B
    const int SM2 = 8192 * (int)sizeof(u64);       // 65536 B
    cudaFuncSetAttribute(rx_pass1, cudaFuncAttributeMaxDynamicSharedMemorySize, SM1);
    cudaFuncSetAttribute(rx_pass2, cudaFuncAttributeMaxDynamicSharedMemorySize, SM2);

    // Per-8-batch groups: pass2(g) reads pass1(g)'s 64MB output from L2.
    for (int g = 0; g < 2; g++) {
        dim3 grid(128, 8);
        rx_pass1<<<grid, 512, SM1>>>(phi, thetas, out, g * 8);
        rx_pass2<<<grid, 512, SM2>>>(thetas, out, g * 8);
    }
}

// round 7
// speedup vs baseline: 1.8828x; 1.1162x over previous
#include <cuda_runtime.h>

// RX2: apply RX(theta_q) to each of 20 qubits of [16, 2^20] states.
// Stage k pairs amplitudes at stride 2^k and uses qubit 19-k.
//
// Packed (re,im) in 64-bit values, sm_103a f32x2 FMA: 4 fma-pipe instrs
// per butterfly. Pass 1: stages 0..12 (contiguous 8192-amp tiles, 3 smem
// exchanges). Pass 2: stages 13..19 (128 strided rows x 64 contiguous,
// 1 exchange), in place.
//
// 4 groups of 4 batches pipelined across 2 forked streams: p1(g+1)
// overlaps p2(g), covering each kernel's ~40% DRAM / ~25% issue
// latency-boundness. 32MB intermediate per group (2 in flight) stays in
// the 126MB L2 between p1 and p2.

#define NQ 20
typedef unsigned long long u64;

__device__ __forceinline__ u64 pk2(float x, float y) {
    u64 v; asm("mov.b64 %0, {%1, %2};" : "=l"(v) : "f"(x), "f"(y)); return v;
}
__device__ __forceinline__ u64 swp(u64 v) {
    float x, y;
    asm("mov.b64 {%0, %1}, %2;" : "=f"(x), "=f"(y) : "l"(v));
    return pk2(y, x);
}
__device__ __forceinline__ u64 fma2(u64 a, u64 b, u64 c) {
    u64 d; asm("fma.rn.f32x2 %0, %1, %2, %3;" : "=l"(d) : "l"(a), "l"(b), "l"(c)); return d;
}
__device__ __forceinline__ u64 mul2(u64 a, u64 b) {
    u64 d; asm("mul.rn.f32x2 %0, %1, %2;" : "=l"(d) : "l"(a), "l"(b)); return d;
}

// a=(ar,ai), b=(br,bi); c2=(c,c), s2=(s,-s)
// na = c2*a + s2*swap(b) ; nb = c2*b + s2*swap(a)
__device__ __forceinline__ void bfly2(u64& a, u64& b, u64 c2, u64 s2) {
    u64 na = fma2(c2, a, mul2(s2, swp(b)));
    u64 nb = fma2(c2, b, mul2(s2, swp(a)));
    a = na; b = nb;
}

// -------------------------------------------------------------------------
// Pass 1: stages 0..12 (qubits 19..7). Tile = 8192 contiguous amplitudes.
// 512 threads, 16 amps/thread. Rounds: bits 0-3 / 4-7 / 8-11; final stage
// (bit 12) fused with the global store. Pad p = i + (i>>4).
// -------------------------------------------------------------------------
__global__ __launch_bounds__(512, 2)
void rx_pass1(const float* __restrict__ phi,
              const float* __restrict__ thetas,
              u64* __restrict__ out, int b0)
{
    extern __shared__ u64 sm[];              // 8704 u64
    __shared__ u64 c2B[13], s2B[13];

    const int t    = threadIdx.x;
    const int b    = b0 + blockIdx.y;
    const int tile = blockIdx.x;
    const size_t base = ((size_t)b << 20) + ((size_t)tile << 13);

    if (t < 13) {
        float sv, cv;
        sincosf(0.5f * thetas[b * NQ + (19 - t)], &sv, &cv);
        c2B[t] = pk2(cv, cv);
        s2B[t] = pk2(sv, -sv);
    }

    u64 amp[16];

    // ---- Round A: load real input (read-once: evict-first), idx = 16*t+j ----
    const float4* pin = (const float4*)(phi + base + ((size_t)t << 4));
    #pragma unroll
    for (int q = 0; q < 4; q++) {
        float4 v = __ldcs(pin + q);
        amp[4*q+0] = pk2(v.x, 0.f);
        amp[4*q+1] = pk2(v.y, 0.f);
        amp[4*q+2] = pk2(v.z, 0.f);
        amp[4*q+3] = pk2(v.w, 0.f);
    }
    __syncthreads();   // c2B/s2B visible

    #pragma unroll
    for (int k = 0; k < 4; k++) {
        const u64 c2 = c2B[k], s2 = s2B[k];
        const int m = 1 << k;
        #pragma unroll
        for (int j = 0; j < 16; j++)
            if (!(j & m)) bfly2(amp[j], amp[j | m], c2, s2);
    }
    #pragma unroll
    for (int j = 0; j < 16; j++) {
        int i = (t << 4) + j;
        sm[i + (i >> 4)] = amp[j];
    }
    __syncthreads();

    // ---- Round B: idx = (t&15) | (j<<4) | ((t>>4)<<8) ----
    #pragma unroll
    for (int j = 0; j < 16; j++) {
        int i = (t & 15) | (j << 4) | ((t >> 4) << 8);
        amp[j] = sm[i + (i >> 4)];
    }
    #pragma unroll
    for (int k = 4; k < 8; k++) {
        const u64 c2 = c2B[k], s2 = s2B[k];
        const int m = 1 << (k - 4);
        #pragma unroll
        for (int j = 0; j < 16; j++)
            if (!(j & m)) bfly2(amp[j], amp[j | m], c2, s2);
    }
    __syncthreads();
    #pragma unroll
    for (int j = 0; j < 16; j++) {
        int i = (t & 15) | (j << 4) | ((t >> 4) << 8);
        sm[i + (i >> 4)] = amp[j];
    }
    __syncthreads();

    // ---- Round C: idx = (t&255) | (j<<8) | ((t>>8)<<12) ----
    #pragma unroll
    for (int j = 0; j < 16; j++) {
        int i = (t & 255) | (j << 8) | ((t >> 8) << 12);
        amp[j] = sm[i + (i >> 4)];
    }
    #pragma unroll
    for (int k = 8; k < 12; k++) {
        const u64 c2 = c2B[k], s2 = s2B[k];
        const int m = 1 << (k - 8);
        #pragma unroll
        for (int j = 0; j < 16; j++)
            if (!(j & m)) bfly2(amp[j], amp[j | m], c2, s2);
    }
    __syncthreads();
    #pragma unroll
    for (int j = 0; j < 16; j++) {
        int i = (t & 255) | (j << 8) | ((t >> 8) << 12);
        sm[i + (i >> 4)] = amp[j];
    }
    __syncthreads();

    // ---- Final stage: bit 12, fused with coalesced b64 store (L2-resident:
    //      pass2 re-reads this) ----
    {
        u64* po = out + base;
        const u64 c2 = c2B[12], s2 = s2B[12];
        #pragma unroll
        for (int jj = 0; jj < 8; jj++) {
            int p  = (jj << 9) + t;          // 0..4095, warp-consecutive
            int pb = p + 4096;
            u64 a  = sm[p  + (p  >> 4)];
            u64 bb = sm[pb + (pb >> 4)];
            bfly2(a, bb, c2, s2);
            po[p]  = a;
            po[pb] = bb;
        }
    }
}

// -------------------------------------------------------------------------
// Pass 2: stages 13..19 (qubits 6..0), in place on out.
// Tile: h = 0..127 (bits 13..19) x 64 contiguous. 512 threads, 16 amps,
// one smem exchange. Final stores use .cs (never re-read).
// -------------------------------------------------------------------------
__global__ __launch_bounds__(512, 2)
void rx_pass2(const float* __restrict__ thetas,
              u64* __restrict__ out, int b0)
{
    extern __shared__ u64 sm2[];             // 8192 u64
    __shared__ u64 c2B[7], s2B[7];

    const int t     = threadIdx.x;
    const int b     = b0 + blockIdx.y;
    const int chunk = blockIdx.x;            // idx bits 6..12

    if (t < 7) {
        float sv, cv;
        sincosf(0.5f * thetas[b * NQ + (6 - t)], &sv, &cv);
        c2B[t] = pk2(cv, cv);
        s2B[t] = pk2(sv, -sv);
    }

    u64* pg = out + ((size_t)b << 20) + ((size_t)chunk << 6);
    const int c  = t & 63;
    const int h0 = t >> 6;                   // 0..7

    u64 amp[16];

    // ---- Round A: h = j | (h0<<4) ; 512B-per-warp coalesced b64 loads ----
    #pragma unroll
    for (int j = 0; j < 16; j++) {
        int h = j | (h0 << 4);
        amp[j] = pg[((size_t)h << 13) + c];
    }
    __syncthreads();   // c2B/s2B visible

    #pragma unroll
    for (int m = 0; m < 4; m++) {
        const u64 c2 = c2B[m], s2 = s2B[m];
        const int st = 1 << m;
        #pragma unroll
        for (int j = 0; j < 16; j++)
            if (!(j & st)) bfly2(amp[j], amp[j | st], c2, s2);
    }
    #pragma unroll
    for (int j = 0; j < 16; j++) {
        int h = j | (h0 << 4);
        sm2[(h << 6) + c] = amp[j];
    }
    __syncthreads();

    // ---- Round B: h = h0 | (j<<3) ----
    #pragma unroll
    for (int j = 0; j < 16; j++) {
        int h = h0 | (j << 3);
        amp[j] = sm2[(h << 6) + c];
    }
    #pragma unroll
    for (int m = 4; m < 7; m++) {
        const u64 c2 = c2B[m], s2 = s2B[m];
        const int st = 1 << (m - 3);
        #pragma unroll
        for (int j = 0; j < 16; j++)
            if (!(j & st)) bfly2(amp[j], amp[j | st], c2, s2);
    }
    // ---- final store: streaming (evict-first) ----
    #pragma unroll
    for (int j = 0; j < 16; j++) {
        int h = h0 | (j << 3);
        __stcs((long long*)(pg + (((size_t)h << 13) + c)), (long long)amp[j]);
    }
}

extern "C" void kernel_launch(void* const* d_in, const int* in_sizes, int n_in,
                              void* d_out, int out_size)
{
    const float* phi    = (const float*)d_in[0];   // [16, 2^20] float32
    const float* thetas = (const float*)d_in[1];   // [16, 20]   float32
    u64* out = (u64*)d_out;                        // [16, 2^20] packed (re,im)

    const int SM1 = 8704 * (int)sizeof(u64);       // 69632 B
    const int SM2 = 8192 * (int)sizeof(u64);       // 65536 B
    cudaFuncSetAttribute(rx_pass1, cudaFuncAttributeMaxDynamicSharedMemorySize, SM1);
    cudaFuncSetAttribute(rx_pass2, cudaFuncAttributeMaxDynamicSharedMemorySize, SM2);

    // Host-side stream/event resources (created once; host objects, no device
    // memory). Work enqueued is identical on every call.
    static cudaStream_t s[2] = {nullptr, nullptr};
    static cudaEvent_t eRoot = nullptr, eDone[2] = {nullptr, nullptr};
    if (!s[0]) {
        cudaStreamCreateWithFlags(&s[0], cudaStreamNonBlocking);
        cudaStreamCreateWithFlags(&s[1], cudaStreamNonBlocking);
        cudaEventCreateWithFlags(&eRoot,    cudaEventDisableTiming);
        cudaEventCreateWithFlags(&eDone[0], cudaEventDisableTiming);
        cudaEventCreateWithFlags(&eDone[1], cudaEventDisableTiming);
    }

    // Fork both worker streams off the (capturing) launch stream.
    cudaEventRecord(eRoot, 0);
    cudaStreamWaitEvent(s[0], eRoot, 0);
    cudaStreamWaitEvent(s[1], eRoot, 0);

    // 4 groups of 4 batches; group g on stream g&1. Within a stream,
    // p1(g) -> p2(g) order is implicit; across streams, groups overlap.
    for (int g = 0; g < 4; g++) {
        cudaStream_t st = s[g & 1];
        dim3 grid(128, 4);
        rx_pass1<<<grid, 512, SM1, st>>>(phi, thetas, out, g * 4);
        rx_pass2<<<grid, 512, SM2, st>>>(thetas, out, g * 4);
    }

    // Join back into the launch stream.
    cudaEventRecord(eDone[0], s[0]);
    cudaEventRecord(eDone[1], s[1]);
    cudaStreamWaitEvent(0, eDone[0], 0);
    cudaStreamWaitEvent(0, eDone[1], 0);
}